// round 1
// baseline (speedup 1.0000x reference)
#include <cuda_runtime.h>
#include <cuda_fp16.h>
#include <mma.h>
using namespace nvcuda;

// Problem dims (fixed by the dataset)
#define B_    2
#define S_    2048
#define D_    2048
#define H_    16
#define DH_   128
#define DFF_  8192
#define DHP_  160           // 129-dim lorentz q/k padded to multiple of 32
#define BH_   32            // B_*H_
#define NROWS 4096          // B_*S_

// ---------------- scratch (static device globals; no allocs) ----------------
__device__ float  g_v  [(size_t)NROWS*D_];     // log_map(x)
__device__ __half g_u1 [(size_t)NROWS*D_];     // rmsnormed log vector (attn / ffn input)
__device__ __half g_wq [(size_t)D_*D_];
__device__ __half g_wk [(size_t)D_*D_];
__device__ __half g_wv [(size_t)D_*D_];
__device__ __half g_wo [(size_t)D_*D_];
__device__ __half g_w1 [(size_t)D_*DFF_];
__device__ __half g_w2 [(size_t)DFF_*D_];
__device__ __half g_q  [(size_t)NROWS*D_];
__device__ __half g_kk [(size_t)NROWS*D_];
__device__ __half g_vr [(size_t)NROWS*D_];
__device__ __half g_qh [(size_t)BH_*S_*DHP_];  // lorentz-lifted q, head-major
__device__ __half g_kh [(size_t)BH_*S_*DHP_];
__device__ __half g_vh [(size_t)BH_*S_*DH_];   // v, head-major
__device__ __half g_sc [(size_t)BH_*S_*S_];    // scores (masked, scaled)
__device__ __half g_pm [(size_t)BH_*S_*S_];    // softmax probs
__device__ __half g_ao [(size_t)NROWS*D_];     // attn out, [b,s,h*dh]
__device__ float  g_u2 [(size_t)NROWS*D_];     // v + attn@Wo
__device__ __half g_hid[(size_t)NROWS*DFF_];   // gelu(ffn hidden)
__device__ float  g_uf [(size_t)NROWS*D_];     // u2 + ffn_pre

// ---------------- reductions ----------------
__device__ __forceinline__ float warpSum(float v){
#pragma unroll
  for (int o=16;o>0;o>>=1) v += __shfl_xor_sync(0xffffffffu, v, o);
  return v;
}
__device__ __forceinline__ float warpMax(float v){
#pragma unroll
  for (int o=16;o>0;o>>=1) v = fmaxf(v, __shfl_xor_sync(0xffffffffu, v, o));
  return v;
}
__device__ float blockSum(float v){
  __shared__ float sh[9];
  int lane = threadIdx.x & 31, wid = threadIdx.x >> 5;
  v = warpSum(v);
  __syncthreads();
  if (lane == 0) sh[wid] = v;
  __syncthreads();
  if (wid == 0){
    float r = (lane < 8) ? sh[lane] : 0.f;
    r = warpSum(r);
    if (lane == 0) sh[8] = r;
  }
  __syncthreads();
  return sh[8];
}
__device__ float blockMax(float v){
  __shared__ float sm[9];
  int lane = threadIdx.x & 31, wid = threadIdx.x >> 5;
  v = warpMax(v);
  __syncthreads();
  if (lane == 0) sm[wid] = v;
  __syncthreads();
  if (wid == 0){
    float r = (lane < 8) ? sm[lane] : -3.0e38f;
    r = warpMax(r);
    if (lane == 0) sm[8] = r;
  }
  __syncthreads();
  return sm[8];
}

// ---------------- small kernels ----------------
__global__ void f2h(const float* __restrict__ s, __half* __restrict__ d, int n){
  int i = blockIdx.x * blockDim.x + threadIdx.x;
  if (i < n) d[i] = __float2half(s[i]);
}

// per-row: v = log_map(x); u1 = scale1 * v / rms(v)
__global__ void prep1(const float* __restrict__ x, const float* __restrict__ scale1){
  int row = blockIdx.x, t = threadIdx.x;
  const float* xr = x + (size_t)row*2049 + 1;
  float xi[8]; float ss = 0.f;
#pragma unroll
  for (int j=0;j<8;j++){ xi[j] = xr[t + j*256]; ss += xi[j]*xi[j]; }
  ss = blockSum(ss);
  float n = sqrtf(ss);
  float f = (n < 1e-6f) ? (1.0f - n*n/6.0f) : (asinhf(n) / fmaxf(n, 1e-12f));
  float rinv = 1.0f / sqrtf(f*f*ss*(1.0f/D_) + 1e-6f);
#pragma unroll
  for (int j=0;j<8;j++){
    int c = t + j*256;
    float v = f * xi[j];
    g_v [(size_t)row*D_ + c] = v;
    g_u1[(size_t)row*D_ + c] = __float2half(scale1[c] * v * rinv);
  }
}

// per (b,s): lift q,k to lorentz (129 dims, padded to 160), copy v head-major
__global__ void headprep(const float* __restrict__ headK){
  int r = blockIdx.x;
  int b = r >> 11, s = r & 2047;
  int wid = threadIdx.x >> 5, lane = threadIdx.x & 31;
#pragma unroll
  for (int rep=0; rep<2; rep++){
    int h = wid*2 + rep;
    int z = b*H_ + h;
    size_t ib = (size_t)r*D_ + (size_t)h*DH_;
    size_t qb = ((size_t)z*S_ + s)*DHP_;
    size_t vb = ((size_t)z*S_ + s)*DH_;
    float Kh = headK[h];
    float sK = sqrtf(-Kh);
    float inv_negK = -1.0f / Kh;
    float qv[4], kv[4]; float ssq = 0.f, ssk = 0.f;
#pragma unroll
    for (int j=0;j<4;j++){
      qv[j] = __half2float(g_q [ib + lane*4 + j]); ssq += qv[j]*qv[j];
      kv[j] = __half2float(g_kk[ib + lane*4 + j]); ssk += kv[j]*kv[j];
      g_vh[vb + lane*4 + j] = g_vr[ib + lane*4 + j];
    }
    ssq = warpSum(ssq); ssk = warpSum(ssk);
    float aq = sK * sqrtf(ssq);
    float sq = (aq < 1e-6f) ? (1.0f + aq*aq/6.0f) : (sinhf(aq)/aq);
    float ak = sK * sqrtf(ssk);
    float sk = (ak < 1e-6f) ? (1.0f + ak*ak/6.0f) : (sinhf(ak)/ak);
#pragma unroll
    for (int j=0;j<4;j++){
      g_qh[qb + lane*4 + j] = __float2half(sq * qv[j]);
      g_kh[qb + lane*4 + j] = __float2half(sk * kv[j]);
    }
    float x0q = sqrtf(inv_negK + sq*sq*ssq);
    float x0k = sqrtf(inv_negK + sk*sk*ssk);
    g_qh[qb + 128 + lane] = (lane==0) ? __float2half(-x0q) : __float2half(0.f);
    g_kh[qb + 128 + lane] = (lane==0) ? __float2half( x0k) : __float2half(0.f);
  }
}

__global__ void softmaxk(){
  int q = blockIdx.x, z = blockIdx.y, t = threadIdx.x;
  size_t base = ((size_t)z*S_ + q)*S_;
  float v[8]; float mx = -3.0e38f;
#pragma unroll
  for (int j=0;j<8;j++){ v[j] = __half2float(g_sc[base + t + j*256]); mx = fmaxf(mx, v[j]); }
  mx = blockMax(mx);
  float s = 0.f;
#pragma unroll
  for (int j=0;j<8;j++){ v[j] = __expf(v[j] - mx); s += v[j]; }
  s = blockSum(s);
  float inv = 1.0f / s;
#pragma unroll
  for (int j=0;j<8;j++) g_pm[base + t + j*256] = __float2half(v[j] * inv);
}

// per-row: u1 = scale2 * u2 / rms(u2)
__global__ void prep2(const float* __restrict__ scale2){
  int row = blockIdx.x, t = threadIdx.x;
  float u[8]; float ss = 0.f;
#pragma unroll
  for (int j=0;j<8;j++){ u[j] = g_u2[(size_t)row*D_ + t + j*256]; ss += u[j]*u[j]; }
  ss = blockSum(ss);
  float rinv = 1.0f / sqrtf(ss*(1.0f/D_) + 1e-6f);
#pragma unroll
  for (int j=0;j<8;j++){
    int c = t + j*256;
    g_u1[(size_t)row*D_ + c] = __float2half(scale2[c] * u[j] * rinv);
  }
}

// per-row: out = exp_map(uf), K=-1
__global__ void finalk(float* __restrict__ out){
  int row = blockIdx.x, t = threadIdx.x;
  float u[8]; float ss = 0.f;
#pragma unroll
  for (int j=0;j<8;j++){ u[j] = g_uf[(size_t)row*D_ + t + j*256]; ss += u[j]*u[j]; }
  ss = blockSum(ss);
  float n = sqrtf(ss);
  float sinc = (n < 1e-6f) ? (1.0f + n*n/6.0f) : (sinhf(n)/n);
  float* o = out + (size_t)row*2049;
  if (t == 0) o[0] = sqrtf(1.0f + sinc*sinc*ss);
#pragma unroll
  for (int j=0;j<8;j++) o[1 + t + j*256] = sinc * u[j];
}

// ---------------- generic wmma GEMM (fp16 in, fp32 accum) ----------------
enum { M_HALF = 0, M_SCORES = 1, M_PV = 2, M_WO = 3, M_GELU = 4, M_W2 = 5 };

template<int MODE>
__global__ __launch_bounds__(256, 2) void gemm_k(
    const __half* __restrict__ A, const __half* __restrict__ Bm,
    void* __restrict__ C, const float* __restrict__ aux,
    int M, int N, int K, int lda, int ldb, int ldc,
    long long strA, long long strB, long long strC)
{
  constexpr bool BT = (MODE == M_SCORES);   // scores: C = A @ B^T
  alignas(32) __shared__ __half As[128*40];
  alignas(32) __shared__ __half Bs[5120];
  alignas(32) __shared__ float  Es[8*16*20];

  const int z = blockIdx.z;
  const __half* Ab = A  + (size_t)z * strA;
  const __half* Bb = Bm + (size_t)z * strB;
  const int rm0 = blockIdx.y * 128;
  const int cn0 = blockIdx.x * 128;
  const int tid = threadIdx.x;
  const int wid = tid >> 5, lane = tid & 31;
  const int wm = wid >> 1, wn = wid & 1;

  if constexpr (MODE == M_SCORES){
    // fully-masked tile: fill and skip GEMM (causal)
    if (cn0 > rm0 + 127){
      __half* Cs = (__half*)C + (size_t)z * strC;
      const __half neg = __float2half(-60000.0f);
      for (int i = tid; i < 128*128; i += 256){
        int r = i >> 7, c = i & 127;
        Cs[(size_t)(rm0 + r) * ldc + cn0 + c] = neg;
      }
      return;
    }
  }

  wmma::fragment<wmma::accumulator,16,16,16,float> fc[2][4];
#pragma unroll
  for (int i=0;i<2;i++)
#pragma unroll
    for (int j=0;j<4;j++) wmma::fill_fragment(fc[i][j], 0.0f);

  for (int k0 = 0; k0 < K; k0 += 32){
    __syncthreads();
#pragma unroll
    for (int it=0; it<2; it++){
      int jj = tid + it*256;
      int r = jj >> 2, c8 = jj & 3;
      const float4* src = reinterpret_cast<const float4*>(Ab + (size_t)(rm0+r)*lda + k0) + c8;
      *reinterpret_cast<float4*>(&As[r*40 + c8*8]) = *src;
    }
    if constexpr (!BT){
#pragma unroll
      for (int it=0; it<2; it++){
        int jj = tid + it*256;
        int r = jj >> 4, c8 = jj & 15;
        const float4* src = reinterpret_cast<const float4*>(Bb + (size_t)(k0+r)*ldb + cn0) + c8;
        *reinterpret_cast<float4*>(&Bs[r*136 + c8*8]) = *src;
      }
    } else {
#pragma unroll
      for (int it=0; it<2; it++){
        int jj = tid + it*256;
        int nn = jj >> 2, c8 = jj & 3;
        const float4* src = reinterpret_cast<const float4*>(Bb + (size_t)(cn0+nn)*ldb + k0) + c8;
        *reinterpret_cast<float4*>(&Bs[nn*40 + c8*8]) = *src;
      }
    }
    __syncthreads();
#pragma unroll
    for (int kk=0; kk<32; kk+=16){
      wmma::fragment<wmma::matrix_a,16,16,16,__half,wmma::row_major> fa[2];
#pragma unroll
      for (int i=0;i<2;i++)
        wmma::load_matrix_sync(fa[i], &As[(wm*32 + i*16)*40 + kk], 40);
      if constexpr (!BT){
#pragma unroll
        for (int j=0;j<4;j++){
          wmma::fragment<wmma::matrix_b,16,16,16,__half,wmma::row_major> fb;
          wmma::load_matrix_sync(fb, &Bs[kk*136 + wn*64 + j*16], 136);
#pragma unroll
          for (int i=0;i<2;i++) wmma::mma_sync(fc[i][j], fa[i], fb, fc[i][j]);
        }
      } else {
#pragma unroll
        for (int j=0;j<4;j++){
          wmma::fragment<wmma::matrix_b,16,16,16,__half,wmma::col_major> fb;
          wmma::load_matrix_sync(fb, &Bs[(wn*64 + j*16)*40 + kk], 40);
#pragma unroll
          for (int i=0;i<2;i++) wmma::mma_sync(fc[i][j], fa[i], fb, fc[i][j]);
        }
      }
    }
  }

  // epilogue: stage each 16x16 accumulator tile through shared, apply MODE op
  float* es = Es + wid*320;
#pragma unroll
  for (int mi=0; mi<2; mi++){
#pragma unroll
    for (int nj=0; nj<4; nj++){
      wmma::store_matrix_sync(es, fc[mi][nj], 20, wmma::mem_row_major);
      __syncwarp();
      int gr0 = rm0 + wm*32 + mi*16;
      int gc0 = cn0 + wn*64 + nj*16;
#pragma unroll
      for (int e=0;e<8;e++){
        int r = lane >> 1;
        int c = (lane & 1)*8 + e;
        float val = es[r*20 + c];
        int gr = gr0 + r, gc = gc0 + c;
        size_t idx = (size_t)z*strC + (size_t)gr*ldc + gc;
        if constexpr (MODE == M_HALF){
          ((__half*)C)[idx] = __float2half(val);
        } else if constexpr (MODE == M_SCORES){
          val *= 0.17677669529663687f;                 // 2/sqrt(128)
          if (gc > gr) val = -60000.0f;                // causal mask
          ((__half*)C)[idx] = __float2half(val);
        } else if constexpr (MODE == M_PV){
          int b = z >> 4, h = z & 15;
          ((__half*)C)[((size_t)(b*S_ + gr))*D_ + (size_t)h*DH_ + gc] = __float2half(val);
        } else if constexpr (MODE == M_WO){
          size_t i2 = (size_t)gr*ldc + gc;
          ((float*)C)[i2] = val + aux[i2];             // u2 = v + attn@Wo
        } else if constexpr (MODE == M_GELU){
          float g = 0.5f*val*(1.0f + erff(val*0.70710678118654752f));
          ((__half*)C)[idx] = __float2half(g);
        } else {                                       // M_W2
          size_t i2 = (size_t)gr*ldc + gc;
          ((float*)C)[i2] = val + aux[i2];             // uf = u2 + ffn_pre
        }
      }
      __syncwarp();
    }
  }
}

// ---------------- host ----------------
static void* symaddr(const void* s){
  void* p = nullptr;
  cudaGetSymbolAddress(&p, s);
  return p;
}

extern "C" void kernel_launch(void* const* d_in, const int* in_sizes, int n_in,
                              void* d_out, int out_size) {
  const float* x      = (const float*)d_in[0];
  // d_in[1] = mask (causal tril; handled analytically)
  const float* scale1 = (const float*)d_in[2];
  const float* scale2 = (const float*)d_in[3];
  const float* Wq     = (const float*)d_in[4];
  const float* Wk     = (const float*)d_in[5];
  const float* Wv     = (const float*)d_in[6];
  const float* Wo     = (const float*)d_in[7];
  const float* headK  = (const float*)d_in[8];
  const float* W1     = (const float*)d_in[9];
  const float* W2     = (const float*)d_in[10];

  __half* wq = (__half*)symaddr(g_wq);
  __half* wk = (__half*)symaddr(g_wk);
  __half* wv = (__half*)symaddr(g_wv);
  __half* wo = (__half*)symaddr(g_wo);
  __half* w1 = (__half*)symaddr(g_w1);
  __half* w2 = (__half*)symaddr(g_w2);
  __half* u1 = (__half*)symaddr(g_u1);
  __half* qh = (__half*)symaddr(g_qh);
  __half* kh = (__half*)symaddr(g_kh);
  __half* vh = (__half*)symaddr(g_vh);
  __half* pm = (__half*)symaddr(g_pm);
  __half* ao = (__half*)symaddr(g_ao);
  __half* hid= (__half*)symaddr(g_hid);
  void*   qq = symaddr(g_q);
  void*   kkp= symaddr(g_kk);
  void*   vr = symaddr(g_vr);
  void*   sc = symaddr(g_sc);
  void*   u2 = symaddr(g_u2);
  void*   uf = symaddr(g_uf);
  const float* vlog = (const float*)symaddr(g_v);

  // 1) weights fp32 -> fp16
  f2h<<<(D_*D_  +255)/256,256>>>(Wq, wq, D_*D_);
  f2h<<<(D_*D_  +255)/256,256>>>(Wk, wk, D_*D_);
  f2h<<<(D_*D_  +255)/256,256>>>(Wv, wv, D_*D_);
  f2h<<<(D_*D_  +255)/256,256>>>(Wo, wo, D_*D_);
  f2h<<<(D_*DFF_+255)/256,256>>>(W1, w1, D_*DFF_);
  f2h<<<(D_*DFF_+255)/256,256>>>(W2, w2, DFF_*D_);

  // 2) log map + rmsnorm-in-log-space
  prep1<<<NROWS,256>>>(x, scale1);

  // 3) QKV projections
  gemm_k<M_HALF><<<dim3(16,32,1),256>>>(u1, wq, qq,  nullptr, NROWS, D_, D_, D_, D_, D_, 0,0,0);
  gemm_k<M_HALF><<<dim3(16,32,1),256>>>(u1, wk, kkp, nullptr, NROWS, D_, D_, D_, D_, D_, 0,0,0);
  gemm_k<M_HALF><<<dim3(16,32,1),256>>>(u1, wv, vr,  nullptr, NROWS, D_, D_, D_, D_, D_, 0,0,0);

  // 4) lift q,k to lorentz 129-dim, v -> head-major
  headprep<<<NROWS,256>>>(headK);

  // 5) scores = (2/sqrt(128)) * q~ . k~, causal mask  (batched over B*H)
  gemm_k<M_SCORES><<<dim3(16,16,BH_),256>>>(qh, kh, sc, nullptr,
      S_, S_, DHP_, DHP_, DHP_, S_,
      (long long)S_*DHP_, (long long)S_*DHP_, (long long)S_*S_);

  // 6) softmax per row
  softmaxk<<<dim3(S_,BH_),256>>>();

  // 7) P @ V  (epilogue writes directly into [b,s,h*dh])
  gemm_k<M_PV><<<dim3(1,16,BH_),256>>>(pm, vh, ao, nullptr,
      S_, DH_, S_, S_, DH_, DH_,
      (long long)S_*S_, (long long)S_*DH_, 0);

  // 8) attn @ Wo + residual(v) -> u2
  gemm_k<M_WO><<<dim3(16,32,1),256>>>(ao, wo, u2, vlog,
      NROWS, D_, D_, D_, D_, D_, 0,0,0);

  // 9) rmsnorm in log space (u2)
  prep2<<<NROWS,256>>>(scale2);

  // 10) FFN: gelu(u1 @ W1)
  gemm_k<M_GELU><<<dim3(64,32,1),256>>>(u1, w1, hid, nullptr,
      NROWS, DFF_, D_, D_, DFF_, DFF_, 0,0,0);

  // 11) hid @ W2 + residual(u2) -> uf
  gemm_k<M_W2><<<dim3(16,32,1),256>>>(hid, w2, uf, (const float*)u2,
      NROWS, D_, DFF_, DFF_, D_, D_, 0,0,0);

  // 12) final exp map -> output (B,S,2049)
  finalk<<<NROWS,256>>>((float*)d_out);
}

// round 3
// speedup vs baseline: 1.1664x; 1.1664x over previous
#include <cuda_runtime.h>
#include <cuda_fp16.h>
#include <mma.h>
using namespace nvcuda;

// Problem dims (fixed by the dataset)
#define B_    2
#define S_    2048
#define D_    2048
#define H_    16
#define DH_   128
#define DFF_  8192
#define DHP_  160           // 129-dim lorentz q/k padded to multiple of 32
#define BH_   32            // B_*H_
#define NROWS 4096          // B_*S_

// ---------------- scratch (static device globals; no allocs) ----------------
__device__ float  g_v  [(size_t)NROWS*D_];     // log_map(x)
__device__ __half g_u1 [(size_t)NROWS*D_];     // rmsnormed log vector (attn / ffn input)
__device__ __half g_wq [(size_t)D_*D_];
__device__ __half g_wk [(size_t)D_*D_];
__device__ __half g_wv [(size_t)D_*D_];
__device__ __half g_wo [(size_t)D_*D_];
__device__ __half g_w1 [(size_t)D_*DFF_];
__device__ __half g_w2 [(size_t)DFF_*D_];
__device__ __half g_q  [(size_t)NROWS*D_];
__device__ __half g_kk [(size_t)NROWS*D_];
__device__ __half g_vr [(size_t)NROWS*D_];
__device__ __half g_qh [(size_t)BH_*S_*DHP_];  // lorentz-lifted q, head-major
__device__ __half g_kh [(size_t)BH_*S_*DHP_];
__device__ __half g_vh [(size_t)BH_*S_*DH_];   // v, head-major
__device__ __half g_sc [(size_t)BH_*S_*S_];    // scores (masked, scaled)
__device__ __half g_pm [(size_t)BH_*S_*S_];    // softmax probs
__device__ __half g_ao [(size_t)NROWS*D_];     // attn out, [b,s,h*dh]
__device__ float  g_u2 [(size_t)NROWS*D_];     // v + attn@Wo
__device__ __half g_hid[(size_t)NROWS*DFF_];   // gelu(ffn hidden)
__device__ float  g_uf [(size_t)NROWS*D_];     // u2 + ffn_pre

// ---------------- cp.async helpers ----------------
__device__ __forceinline__ void cp16(void* dst, const void* src){
  unsigned d = (unsigned)__cvta_generic_to_shared(dst);
  asm volatile("cp.async.cg.shared.global [%0], [%1], 16;" :: "r"(d), "l"(src));
}
__device__ __forceinline__ void cp_commit(){
  asm volatile("cp.async.commit_group;");
}
template<int N> __device__ __forceinline__ void cp_wait(){
  asm volatile("cp.async.wait_group %0;" :: "n"(N));
}

// ---------------- reductions ----------------
__device__ __forceinline__ float warpSum(float v){
#pragma unroll
  for (int o=16;o>0;o>>=1) v += __shfl_xor_sync(0xffffffffu, v, o);
  return v;
}
__device__ __forceinline__ float warpMax(float v){
#pragma unroll
  for (int o=16;o>0;o>>=1) v = fmaxf(v, __shfl_xor_sync(0xffffffffu, v, o));
  return v;
}
__device__ float blockSum(float v){
  __shared__ float sh[9];
  int lane = threadIdx.x & 31, wid = threadIdx.x >> 5;
  v = warpSum(v);
  __syncthreads();
  if (lane == 0) sh[wid] = v;
  __syncthreads();
  if (wid == 0){
    float r = (lane < 8) ? sh[lane] : 0.f;
    r = warpSum(r);
    if (lane == 0) sh[8] = r;
  }
  __syncthreads();
  return sh[8];
}
__device__ float blockMax(float v){
  __shared__ float sm[9];
  int lane = threadIdx.x & 31, wid = threadIdx.x >> 5;
  v = warpMax(v);
  __syncthreads();
  if (lane == 0) sm[wid] = v;
  __syncthreads();
  if (wid == 0){
    float r = (lane < 8) ? sm[lane] : -3.0e38f;
    r = warpMax(r);
    if (lane == 0) sm[8] = r;
  }
  __syncthreads();
  return sm[8];
}

// ---------------- small kernels ----------------
// vectorized fp32 -> fp16 (8 elems / thread); n must be a multiple of 8
__global__ void f2h(const float* __restrict__ s, __half* __restrict__ d, int n){
  int i = (blockIdx.x * blockDim.x + threadIdx.x) * 8;
  if (i < n){
    float4 a = *reinterpret_cast<const float4*>(s + i);
    float4 b = *reinterpret_cast<const float4*>(s + i + 4);
    __half h[8];
    h[0]=__float2half(a.x); h[1]=__float2half(a.y); h[2]=__float2half(a.z); h[3]=__float2half(a.w);
    h[4]=__float2half(b.x); h[5]=__float2half(b.y); h[6]=__float2half(b.z); h[7]=__float2half(b.w);
    *reinterpret_cast<int4*>(d + i) = *reinterpret_cast<int4*>(h);
  }
}

// per-row: v = log_map(x); u1 = scale1 * v / rms(v)
__global__ void prep1(const float* __restrict__ x, const float* __restrict__ scale1){
  int row = blockIdx.x, t = threadIdx.x;
  const float* xr = x + (size_t)row*2049 + 1;
  float xi[8]; float ss = 0.f;
#pragma unroll
  for (int j=0;j<8;j++){ xi[j] = xr[t + j*256]; ss += xi[j]*xi[j]; }
  ss = blockSum(ss);
  float n = sqrtf(ss);
  float f = (n < 1e-6f) ? (1.0f - n*n/6.0f) : (asinhf(n) / fmaxf(n, 1e-12f));
  float rinv = 1.0f / sqrtf(f*f*ss*(1.0f/D_) + 1e-6f);
#pragma unroll
  for (int j=0;j<8;j++){
    int c = t + j*256;
    float v = f * xi[j];
    g_v [(size_t)row*D_ + c] = v;
    g_u1[(size_t)row*D_ + c] = __float2half(scale1[c] * v * rinv);
  }
}

// per (b,s): lift q,k to lorentz (129 dims, padded to 160), copy v head-major
__global__ void headprep(const float* __restrict__ headK){
  int r = blockIdx.x;
  int b = r >> 11, s = r & 2047;
  int wid = threadIdx.x >> 5, lane = threadIdx.x & 31;
#pragma unroll
  for (int rep=0; rep<2; rep++){
    int h = wid*2 + rep;
    int z = b*H_ + h;
    size_t ib = (size_t)r*D_ + (size_t)h*DH_;
    size_t qb = ((size_t)z*S_ + s)*DHP_;
    size_t vb = ((size_t)z*S_ + s)*DH_;
    float Kh = headK[h];
    float sK = sqrtf(-Kh);
    float inv_negK = -1.0f / Kh;
    float qv[4], kv[4]; float ssq = 0.f, ssk = 0.f;
#pragma unroll
    for (int j=0;j<4;j++){
      qv[j] = __half2float(g_q [ib + lane*4 + j]); ssq += qv[j]*qv[j];
      kv[j] = __half2float(g_kk[ib + lane*4 + j]); ssk += kv[j]*kv[j];
      g_vh[vb + lane*4 + j] = g_vr[ib + lane*4 + j];
    }
    ssq = warpSum(ssq); ssk = warpSum(ssk);
    float aq = sK * sqrtf(ssq);
    float sq = (aq < 1e-6f) ? (1.0f + aq*aq/6.0f) : (sinhf(aq)/aq);
    float ak = sK * sqrtf(ssk);
    float sk = (ak < 1e-6f) ? (1.0f + ak*ak/6.0f) : (sinhf(ak)/ak);
#pragma unroll
    for (int j=0;j<4;j++){
      g_qh[qb + lane*4 + j] = __float2half(sq * qv[j]);
      g_kh[qb + lane*4 + j] = __float2half(sk * kv[j]);
    }
    float x0q = sqrtf(inv_negK + sq*sq*ssq);
    float x0k = sqrtf(inv_negK + sk*sk*ssk);
    g_qh[qb + 128 + lane] = (lane==0) ? __float2half(-x0q) : __float2half(0.f);
    g_kh[qb + 128 + lane] = (lane==0) ? __float2half( x0k) : __float2half(0.f);
  }
}

// causal-aware softmax: only the first (q&~127)+128 columns exist / matter
__global__ void softmaxk(){
  int q = blockIdx.x, z = blockIdx.y, t = threadIdx.x;
  size_t base = ((size_t)z*S_ + q)*S_;
  int nlim = (q & ~127) + 128;      // multiple of 128; PV reads exactly k < nlim
  float v[8]; float mx = -3.0e38f;
#pragma unroll
  for (int j=0;j<8;j++){
    int c = t + j*256;
    bool ok = c < nlim;
    v[j] = ok ? __half2float(g_sc[base + c]) : -1.0e30f;
    mx = fmaxf(mx, v[j]);
  }
  mx = blockMax(mx);
  float s = 0.f;
#pragma unroll
  for (int j=0;j<8;j++){ v[j] = __expf(v[j] - mx); s += v[j]; }
  s = blockSum(s);
  float inv = 1.0f / s;
#pragma unroll
  for (int j=0;j<8;j++){
    int c = t + j*256;
    if (c < nlim) g_pm[base + c] = __float2half(v[j] * inv);
  }
}

// per-row: u1 = scale2 * u2 / rms(u2)
__global__ void prep2(const float* __restrict__ scale2){
  int row = blockIdx.x, t = threadIdx.x;
  float u[8]; float ss = 0.f;
#pragma unroll
  for (int j=0;j<8;j++){ u[j] = g_u2[(size_t)row*D_ + t + j*256]; ss += u[j]*u[j]; }
  ss = blockSum(ss);
  float rinv = 1.0f / sqrtf(ss*(1.0f/D_) + 1e-6f);
#pragma unroll
  for (int j=0;j<8;j++){
    int c = t + j*256;
    g_u1[(size_t)row*D_ + c] = __float2half(scale2[c] * u[j] * rinv);
  }
}

// per-row: out = exp_map(uf), K=-1
__global__ void finalk(float* __restrict__ out){
  int row = blockIdx.x, t = threadIdx.x;
  float u[8]; float ss = 0.f;
#pragma unroll
  for (int j=0;j<8;j++){ u[j] = g_uf[(size_t)row*D_ + t + j*256]; ss += u[j]*u[j]; }
  ss = blockSum(ss);
  float n = sqrtf(ss);
  float sinc = (n < 1e-6f) ? (1.0f + n*n/6.0f) : (sinhf(n)/n);
  float* o = out + (size_t)row*2049;
  if (t == 0) o[0] = sqrtf(1.0f + sinc*sinc*ss);
#pragma unroll
  for (int j=0;j<8;j++) o[1 + t + j*256] = sinc * u[j];
}

// ---------------- wmma GEMM, cp.async double-buffered ----------------
enum { M_HALF = 0, M_SCORES = 1, M_PV = 2, M_WO = 3, M_GELU = 4, M_W2 = 5 };

template<int MODE>
__global__ __launch_bounds__(256, 2) void gemm_k(
    const __half* __restrict__ A, const __half* __restrict__ Bm,
    void* __restrict__ C, const float* __restrict__ aux,
    int M, int N, int K, int lda, int ldb, int ldc,
    long long strA, long long strB, long long strC)
{
  constexpr bool BT = (MODE == M_SCORES);   // scores: C = A @ B^T
  alignas(16) __shared__ __half As[2][5120];  // 128 x 32 tile, row stride 40
  alignas(16) __shared__ __half Bs[2][5120];  // 32 x 128 (stride 136) or 128 x 32 (stride 40)

  const int z = blockIdx.z;
  const int rm0 = blockIdx.y * 128;
  const int cn0 = blockIdx.x * 128;

  if constexpr (MODE == M_SCORES){
    if (cn0 > rm0 + 127) return;   // fully-masked tile: never read downstream
  }
  if constexpr (MODE == M_PV){
    K = min(K, rm0 + 128);         // causal: P is zero beyond the diagonal tile row
  }

  const __half* Ab = A  + (size_t)z * strA;
  const __half* Bb = Bm + (size_t)z * strB;
  const int tid = threadIdx.x;
  const int wid = tid >> 5, lane = tid & 31;
  const int wm = wid >> 1, wn = wid & 1;
  const int KT = K >> 5;

  // per-thread load coords (2 x 16B each for A and B)
  const int ar0 = tid >> 2,  ac0 = (tid & 3) * 8;           // +64 rows for it=1
  const int br0 = tid >> 4,  bc0 = (tid & 15) * 8;          // K-major B (+16 rows)
  const int tr0 = tid >> 2,  tc0 = (tid & 3) * 8;           // BT B (+64 rows)

  auto loadTile = [&](int kt, int buf){
    int k0 = kt << 5;
#pragma unroll
    for (int it=0; it<2; it++){
      int r = ar0 + it*64;
      cp16(&As[buf][r*40 + ac0], Ab + (size_t)(rm0 + r)*lda + k0 + ac0);
    }
    if constexpr (!BT){
#pragma unroll
      for (int it=0; it<2; it++){
        int r = br0 + it*16;
        cp16(&Bs[buf][r*136 + bc0], Bb + (size_t)(k0 + r)*ldb + cn0 + bc0);
      }
    } else {
#pragma unroll
      for (int it=0; it<2; it++){
        int r = tr0 + it*64;
        cp16(&Bs[buf][r*40 + tc0], Bb + (size_t)(cn0 + r)*ldb + k0 + tc0);
      }
    }
  };

  wmma::fragment<wmma::accumulator,16,16,16,float> fc[2][4];
#pragma unroll
  for (int i=0;i<2;i++)
#pragma unroll
    for (int j=0;j<4;j++) wmma::fill_fragment(fc[i][j], 0.0f);

  loadTile(0, 0); cp_commit();

  for (int kt = 0; kt < KT; kt++){
    cp_wait<0>();
    __syncthreads();
    if (kt + 1 < KT){ loadTile(kt+1, (kt+1)&1); cp_commit(); }
    const int cur = kt & 1;
#pragma unroll
    for (int kk=0; kk<32; kk+=16){
      wmma::fragment<wmma::matrix_a,16,16,16,__half,wmma::row_major> fa[2];
#pragma unroll
      for (int i=0;i<2;i++)
        wmma::load_matrix_sync(fa[i], &As[cur][(wm*32 + i*16)*40 + kk], 40);
      if constexpr (!BT){
#pragma unroll
        for (int j=0;j<4;j++){
          wmma::fragment<wmma::matrix_b,16,16,16,__half,wmma::row_major> fb;
          wmma::load_matrix_sync(fb, &Bs[cur][kk*136 + wn*64 + j*16], 136);
#pragma unroll
          for (int i=0;i<2;i++) wmma::mma_sync(fc[i][j], fa[i], fb, fc[i][j]);
        }
      } else {
#pragma unroll
        for (int j=0;j<4;j++){
          wmma::fragment<wmma::matrix_b,16,16,16,__half,wmma::col_major> fb;
          wmma::load_matrix_sync(fb, &Bs[cur][(wn*64 + j*16)*40 + kk], 40);
#pragma unroll
          for (int i=0;i<2;i++) wmma::mma_sync(fc[i][j], fa[i], fb, fc[i][j]);
        }
      }
    }
    __syncthreads();
  }

  // epilogue: stage each 16x16 accumulator tile through shared (aliases As)
  __syncthreads();
  float* Es = reinterpret_cast<float*>(&As[0][0]);
  float* es = Es + wid*320;
#pragma unroll
  for (int mi=0; mi<2; mi++){
#pragma unroll
    for (int nj=0; nj<4; nj++){
      wmma::store_matrix_sync(es, fc[mi][nj], 20, wmma::mem_row_major);
      __syncwarp();
      int gr0 = rm0 + wm*32 + mi*16;
      int gc0 = cn0 + wn*64 + nj*16;
#pragma unroll
      for (int e=0;e<8;e++){
        int r = lane >> 1;
        int c = (lane & 1)*8 + e;
        float val = es[r*20 + c];
        int gr = gr0 + r, gc = gc0 + c;
        size_t idx = (size_t)z*strC + (size_t)gr*ldc + gc;
        if constexpr (MODE == M_HALF){
          ((__half*)C)[idx] = __float2half(val);
        } else if constexpr (MODE == M_SCORES){
          val *= 0.17677669529663687f;                 // 2/sqrt(128)
          if (gc > gr) val = -60000.0f;                // causal mask
          ((__half*)C)[idx] = __float2half(val);
        } else if constexpr (MODE == M_PV){
          int b = z >> 4, h = z & 15;
          ((__half*)C)[((size_t)(b*S_ + gr))*D_ + (size_t)h*DH_ + gc] = __float2half(val);
        } else if constexpr (MODE == M_WO){
          size_t i2 = (size_t)gr*ldc + gc;
          ((float*)C)[i2] = val + aux[i2];             // u2 = v + attn@Wo
        } else if constexpr (MODE == M_GELU){
          float g = 0.5f*val*(1.0f + erff(val*0.70710678118654752f));
          ((__half*)C)[idx] = __float2half(g);
        } else {                                       // M_W2
          size_t i2 = (size_t)gr*ldc + gc;
          ((float*)C)[i2] = val + aux[i2];             // uf = u2 + ffn_pre
        }
      }
      __syncwarp();
    }
  }
}

// ---------------- host ----------------
static void* symaddr(const void* s){
  void* p = nullptr;
  cudaGetSymbolAddress(&p, s);
  return p;
}

extern "C" void kernel_launch(void* const* d_in, const int* in_sizes, int n_in,
                              void* d_out, int out_size) {
  const float* x      = (const float*)d_in[0];
  // d_in[1] = mask (causal tril; handled analytically)
  const float* scale1 = (const float*)d_in[2];
  const float* scale2 = (const float*)d_in[3];
  const float* Wq     = (const float*)d_in[4];
  const float* Wk     = (const float*)d_in[5];
  const float* Wv     = (const float*)d_in[6];
  const float* Wo     = (const float*)d_in[7];
  const float* headK  = (const float*)d_in[8];
  const float* W1     = (const float*)d_in[9];
  const float* W2     = (const float*)d_in[10];

  __half* wq = (__half*)symaddr(g_wq);
  __half* wk = (__half*)symaddr(g_wk);
  __half* wv = (__half*)symaddr(g_wv);
  __half* wo = (__half*)symaddr(g_wo);
  __half* w1 = (__half*)symaddr(g_w1);
  __half* w2 = (__half*)symaddr(g_w2);
  __half* u1 = (__half*)symaddr(g_u1);
  __half* qh = (__half*)symaddr(g_qh);
  __half* kh = (__half*)symaddr(g_kh);
  __half* vh = (__half*)symaddr(g_vh);
  __half* pm = (__half*)symaddr(g_pm);
  __half* ao = (__half*)symaddr(g_ao);
  __half* hid= (__half*)symaddr(g_hid);
  void*   qq = symaddr(g_q);
  void*   kkp= symaddr(g_kk);
  void*   vr = symaddr(g_vr);
  void*   sc = symaddr(g_sc);
  void*   u2 = symaddr(g_u2);
  void*   uf = symaddr(g_uf);
  const float* vlog = (const float*)symaddr(g_v);

  // 1) weights fp32 -> fp16 (vectorized, 8/thread)
  f2h<<<(D_*D_/8  +255)/256,256>>>(Wq, wq, D_*D_);
  f2h<<<(D_*D_/8  +255)/256,256>>>(Wk, wk, D_*D_);
  f2h<<<(D_*D_/8  +255)/256,256>>>(Wv, wv, D_*D_);
  f2h<<<(D_*D_/8  +255)/256,256>>>(Wo, wo, D_*D_);
  f2h<<<(D_*DFF_/8+255)/256,256>>>(W1, w1, D_*DFF_);
  f2h<<<(D_*DFF_/8+255)/256,256>>>(W2, w2, DFF_*D_);

  // 2) log map + rmsnorm-in-log-space
  prep1<<<NROWS,256>>>(x, scale1);

  // 3) QKV projections
  gemm_k<M_HALF><<<dim3(16,32,1),256>>>(u1, wq, qq,  nullptr, NROWS, D_, D_, D_, D_, D_, 0,0,0);
  gemm_k<M_HALF><<<dim3(16,32,1),256>>>(u1, wk, kkp, nullptr, NROWS, D_, D_, D_, D_, D_, 0,0,0);
  gemm_k<M_HALF><<<dim3(16,32,1),256>>>(u1, wv, vr,  nullptr, NROWS, D_, D_, D_, D_, D_, 0,0,0);

  // 4) lift q,k to lorentz 129-dim, v -> head-major
  headprep<<<NROWS,256>>>(headK);

  // 5) scores = (2/sqrt(128)) * q~ . k~, causal mask (masked tiles skipped)
  gemm_k<M_SCORES><<<dim3(16,16,BH_),256>>>(qh, kh, sc, nullptr,
      S_, S_, DHP_, DHP_, DHP_, S_,
      (long long)S_*DHP_, (long long)S_*DHP_, (long long)S_*S_);

  // 6) softmax per row (causal-bounded)
  softmaxk<<<dim3(S_,BH_),256>>>();

  // 7) P @ V with causal K cap (epilogue writes directly into [b,s,h*dh])
  gemm_k<M_PV><<<dim3(1,16,BH_),256>>>(pm, vh, ao, nullptr,
      S_, DH_, S_, S_, DH_, DH_,
      (long long)S_*S_, (long long)S_*DH_, 0);

  // 8) attn @ Wo + residual(v) -> u2
  gemm_k<M_WO><<<dim3(16,32,1),256>>>(ao, wo, u2, vlog,
      NROWS, D_, D_, D_, D_, D_, 0,0,0);

  // 9) rmsnorm in log space (u2)
  prep2<<<NROWS,256>>>(scale2);

  // 10) FFN: gelu(u1 @ W1)
  gemm_k<M_GELU><<<dim3(64,32,1),256>>>(u1, w1, hid, nullptr,
      NROWS, DFF_, D_, D_, DFF_, DFF_, 0,0,0);

  // 11) hid @ W2 + residual(u2) -> uf
  gemm_k<M_W2><<<dim3(16,32,1),256>>>(hid, w2, uf, (const float*)u2,
      NROWS, D_, DFF_, DFF_, D_, D_, 0,0,0);

  // 12) final exp map -> output (B,S,2049)
  finalk<<<NROWS,256>>>((float*)d_out);
}

// round 4
// speedup vs baseline: 1.4629x; 1.2542x over previous
#include <cuda_runtime.h>
#include <cuda_fp16.h>
#include <mma.h>
using namespace nvcuda;

// Problem dims (fixed by the dataset)
#define B_    2
#define S_    2048
#define D_    2048
#define H_    16
#define DH_   128
#define DFF_  8192
#define DHP_  160           // 129-dim lorentz q/k padded to multiple of 32
#define BH_   32            // B_*H_
#define NROWS 4096          // B_*S_

#define STAGE_H 5120        // halves per smem stage (A or B)
#define NSTAGE  3
#define SMEM_BYTES (NSTAGE * STAGE_H * 2 * 2)   // A + B, 3 stages = 61440 B

// ---------------- scratch (static device globals; no allocs) ----------------
__device__ float  g_v  [(size_t)NROWS*D_];     // log_map(x)
__device__ __half g_u1 [(size_t)NROWS*D_];     // rmsnormed log vector (attn / ffn input)
__device__ __half g_wq [(size_t)D_*D_];
__device__ __half g_wk [(size_t)D_*D_];
__device__ __half g_wv [(size_t)D_*D_];
__device__ __half g_wo [(size_t)D_*D_];
__device__ __half g_w1 [(size_t)D_*DFF_];
__device__ __half g_w2 [(size_t)DFF_*D_];
__device__ __half g_q  [(size_t)NROWS*D_];
__device__ __half g_kk [(size_t)NROWS*D_];
__device__ __half g_vr [(size_t)NROWS*D_];
__device__ __half g_qh [(size_t)BH_*S_*DHP_];  // lorentz-lifted q, head-major
__device__ __half g_kh [(size_t)BH_*S_*DHP_];
__device__ __half g_vh [(size_t)BH_*S_*DH_];   // v, head-major
__device__ __half g_sc [(size_t)BH_*S_*S_];    // scores (masked, scaled)
__device__ __half g_pm [(size_t)BH_*S_*S_];    // softmax probs
__device__ __half g_ao [(size_t)NROWS*D_];     // attn out, [b,s,h*dh]
__device__ float  g_u2 [(size_t)NROWS*D_];     // v + attn@Wo
__device__ __half g_hid[(size_t)NROWS*DFF_];   // gelu(ffn hidden)
__device__ float  g_uf [(size_t)NROWS*D_];     // u2 + ffn_pre

// ---------------- cp.async helpers ----------------
__device__ __forceinline__ void cp16(void* dst, const void* src){
  unsigned d = (unsigned)__cvta_generic_to_shared(dst);
  asm volatile("cp.async.cg.shared.global [%0], [%1], 16;" :: "r"(d), "l"(src));
}
__device__ __forceinline__ void cp_commit(){
  asm volatile("cp.async.commit_group;");
}
template<int N> __device__ __forceinline__ void cp_wait(){
  asm volatile("cp.async.wait_group %0;" :: "n"(N));
}

// ---------------- reductions ----------------
__device__ __forceinline__ float warpSum(float v){
#pragma unroll
  for (int o=16;o>0;o>>=1) v += __shfl_xor_sync(0xffffffffu, v, o);
  return v;
}
__device__ __forceinline__ float warpMax(float v){
#pragma unroll
  for (int o=16;o>0;o>>=1) v = fmaxf(v, __shfl_xor_sync(0xffffffffu, v, o));
  return v;
}
__device__ float blockSum(float v){
  __shared__ float sh[9];
  int lane = threadIdx.x & 31, wid = threadIdx.x >> 5;
  v = warpSum(v);
  __syncthreads();
  if (lane == 0) sh[wid] = v;
  __syncthreads();
  if (wid == 0){
    float r = (lane < 8) ? sh[lane] : 0.f;
    r = warpSum(r);
    if (lane == 0) sh[8] = r;
  }
  __syncthreads();
  return sh[8];
}
__device__ float blockMax(float v){
  __shared__ float sm[9];
  int lane = threadIdx.x & 31, wid = threadIdx.x >> 5;
  v = warpMax(v);
  __syncthreads();
  if (lane == 0) sm[wid] = v;
  __syncthreads();
  if (wid == 0){
    float r = (lane < 8) ? sm[lane] : -3.0e38f;
    r = warpMax(r);
    if (lane == 0) sm[8] = r;
  }
  __syncthreads();
  return sm[8];
}

// ---------------- small kernels ----------------
// vectorized fp32 -> fp16 (8 elems / thread); n must be a multiple of 8
__global__ void f2h(const float* __restrict__ s, __half* __restrict__ d, int n){
  int i = (blockIdx.x * blockDim.x + threadIdx.x) * 8;
  if (i < n){
    float4 a = *reinterpret_cast<const float4*>(s + i);
    float4 b = *reinterpret_cast<const float4*>(s + i + 4);
    __half h[8];
    h[0]=__float2half(a.x); h[1]=__float2half(a.y); h[2]=__float2half(a.z); h[3]=__float2half(a.w);
    h[4]=__float2half(b.x); h[5]=__float2half(b.y); h[6]=__float2half(b.z); h[7]=__float2half(b.w);
    *reinterpret_cast<int4*>(d + i) = *reinterpret_cast<int4*>(h);
  }
}

// per-row: v = log_map(x); u1 = scale1 * v / rms(v)
__global__ void prep1(const float* __restrict__ x, const float* __restrict__ scale1){
  int row = blockIdx.x, t = threadIdx.x;
  const float* xr = x + (size_t)row*2049 + 1;
  float xi[8]; float ss = 0.f;
#pragma unroll
  for (int j=0;j<8;j++){ xi[j] = xr[t + j*256]; ss += xi[j]*xi[j]; }
  ss = blockSum(ss);
  float n = sqrtf(ss);
  float f = (n < 1e-6f) ? (1.0f - n*n/6.0f) : (asinhf(n) / fmaxf(n, 1e-12f));
  float rinv = 1.0f / sqrtf(f*f*ss*(1.0f/D_) + 1e-6f);
#pragma unroll
  for (int j=0;j<8;j++){
    int c = t + j*256;
    float v = f * xi[j];
    g_v [(size_t)row*D_ + c] = v;
    g_u1[(size_t)row*D_ + c] = __float2half(scale1[c] * v * rinv);
  }
}

// per (b,s): lift q,k to lorentz (129 dims, padded to 160), copy v head-major
__global__ void headprep(const float* __restrict__ headK){
  int r = blockIdx.x;
  int b = r >> 11, s = r & 2047;
  int wid = threadIdx.x >> 5, lane = threadIdx.x & 31;
#pragma unroll
  for (int rep=0; rep<2; rep++){
    int h = wid*2 + rep;
    int z = b*H_ + h;
    size_t ib = (size_t)r*D_ + (size_t)h*DH_;
    size_t qb = ((size_t)z*S_ + s)*DHP_;
    size_t vb = ((size_t)z*S_ + s)*DH_;
    float Kh = headK[h];
    float sK = sqrtf(-Kh);
    float inv_negK = -1.0f / Kh;
    float qv[4], kv[4]; float ssq = 0.f, ssk = 0.f;
#pragma unroll
    for (int j=0;j<4;j++){
      qv[j] = __half2float(g_q [ib + lane*4 + j]); ssq += qv[j]*qv[j];
      kv[j] = __half2float(g_kk[ib + lane*4 + j]); ssk += kv[j]*kv[j];
      g_vh[vb + lane*4 + j] = g_vr[ib + lane*4 + j];
    }
    ssq = warpSum(ssq); ssk = warpSum(ssk);
    float aq = sK * sqrtf(ssq);
    float sq = (aq < 1e-6f) ? (1.0f + aq*aq/6.0f) : (sinhf(aq)/aq);
    float ak = sK * sqrtf(ssk);
    float sk = (ak < 1e-6f) ? (1.0f + ak*ak/6.0f) : (sinhf(ak)/ak);
#pragma unroll
    for (int j=0;j<4;j++){
      g_qh[qb + lane*4 + j] = __float2half(sq * qv[j]);
      g_kh[qb + lane*4 + j] = __float2half(sk * kv[j]);
    }
    float x0q = sqrtf(inv_negK + sq*sq*ssq);
    float x0k = sqrtf(inv_negK + sk*sk*ssk);
    g_qh[qb + 128 + lane] = (lane==0) ? __float2half(-x0q) : __float2half(0.f);
    g_kh[qb + 128 + lane] = (lane==0) ? __float2half( x0k) : __float2half(0.f);
  }
}

// causal-aware softmax: only the first (q&~127)+128 columns exist / matter
__global__ void softmaxk(){
  int q = blockIdx.x, z = blockIdx.y, t = threadIdx.x;
  size_t base = ((size_t)z*S_ + q)*S_;
  int nlim = (q & ~127) + 128;      // multiple of 128; PV reads exactly k < nlim
  float v[8]; float mx = -3.0e38f;
#pragma unroll
  for (int j=0;j<8;j++){
    int c = t + j*256;
    bool ok = c < nlim;
    v[j] = ok ? __half2float(g_sc[base + c]) : -1.0e30f;
    mx = fmaxf(mx, v[j]);
  }
  mx = blockMax(mx);
  float s = 0.f;
#pragma unroll
  for (int j=0;j<8;j++){ v[j] = __expf(v[j] - mx); s += v[j]; }
  s = blockSum(s);
  float inv = 1.0f / s;
#pragma unroll
  for (int j=0;j<8;j++){
    int c = t + j*256;
    if (c < nlim) g_pm[base + c] = __float2half(v[j] * inv);
  }
}

// per-row: u1 = scale2 * u2 / rms(u2)
__global__ void prep2(const float* __restrict__ scale2){
  int row = blockIdx.x, t = threadIdx.x;
  float u[8]; float ss = 0.f;
#pragma unroll
  for (int j=0;j<8;j++){ u[j] = g_u2[(size_t)row*D_ + t + j*256]; ss += u[j]*u[j]; }
  ss = blockSum(ss);
  float rinv = 1.0f / sqrtf(ss*(1.0f/D_) + 1e-6f);
#pragma unroll
  for (int j=0;j<8;j++){
    int c = t + j*256;
    g_u1[(size_t)row*D_ + c] = __float2half(scale2[c] * u[j] * rinv);
  }
}

// per-row: out = exp_map(uf), K=-1
__global__ void finalk(float* __restrict__ out){
  int row = blockIdx.x, t = threadIdx.x;
  float u[8]; float ss = 0.f;
#pragma unroll
  for (int j=0;j<8;j++){ u[j] = g_uf[(size_t)row*D_ + t + j*256]; ss += u[j]*u[j]; }
  ss = blockSum(ss);
  float n = sqrtf(ss);
  float sinc = (n < 1e-6f) ? (1.0f + n*n/6.0f) : (sinhf(n)/n);
  float* o = out + (size_t)row*2049;
  if (t == 0) o[0] = sqrtf(1.0f + sinc*sinc*ss);
#pragma unroll
  for (int j=0;j<8;j++) o[1 + t + j*256] = sinc * u[j];
}

// ---------------- wmma GEMM: 3-stage cp.async, vectorized epilogue ----------------
enum { M_HALF = 0, M_SCORES = 1, M_PV = 2, M_WO = 3, M_GELU = 4, M_W2 = 5 };

template<int MODE>
__global__ __launch_bounds__(256) void gemm_k(
    const __half* __restrict__ A, const __half* __restrict__ Bm,
    void* __restrict__ C, const float* __restrict__ aux,
    int M, int N, int K, int lda, int ldb, int ldc,
    long long strA, long long strB, long long strC)
{
  constexpr bool BT = (MODE == M_SCORES);   // scores: C = A @ B^T
  extern __shared__ __half smem[];
  __half* As = smem;                         // NSTAGE x 5120 (128 x 40)
  __half* Bs = smem + NSTAGE*STAGE_H;        // NSTAGE x 5120

  const int z = blockIdx.z;
  const int rm0 = blockIdx.y * 128;
  const int cn0 = blockIdx.x * 128;

  if constexpr (MODE == M_SCORES){
    if (cn0 > rm0 + 127) return;   // fully-masked tile: never read downstream
  }
  if constexpr (MODE == M_PV){
    K = min(K, rm0 + 128);         // causal: P is zero beyond the diagonal tile row
  }

  const __half* Ab = A  + (size_t)z * strA;
  const __half* Bb = Bm + (size_t)z * strB;
  const int tid = threadIdx.x;
  const int wid = tid >> 5, lane = tid & 31;
  const int wm = wid >> 1, wn = wid & 1;
  const int KT = K >> 5;

  // per-thread load coords (2 x 16B each for A and B)
  const int ar0 = tid >> 2,  ac0 = (tid & 3) * 8;           // +64 rows for it=1
  const int br0 = tid >> 4,  bc0 = (tid & 15) * 8;          // K-major B (+16 rows)
  const int tr0 = tid >> 2,  tc0 = (tid & 3) * 8;           // BT B (+64 rows)

  auto loadTile = [&](int kt, int buf){
    int k0 = kt << 5;
    __half* as = As + buf*STAGE_H;
    __half* bs = Bs + buf*STAGE_H;
#pragma unroll
    for (int it=0; it<2; it++){
      int r = ar0 + it*64;
      cp16(&as[r*40 + ac0], Ab + (size_t)(rm0 + r)*lda + k0 + ac0);
    }
    if constexpr (!BT){
#pragma unroll
      for (int it=0; it<2; it++){
        int r = br0 + it*16;
        cp16(&bs[r*136 + bc0], Bb + (size_t)(k0 + r)*ldb + cn0 + bc0);
      }
    } else {
#pragma unroll
      for (int it=0; it<2; it++){
        int r = tr0 + it*64;
        cp16(&bs[r*40 + tc0], Bb + (size_t)(cn0 + r)*ldb + k0 + tc0);
      }
    }
  };

  wmma::fragment<wmma::accumulator,16,16,16,float> fc[2][4];
#pragma unroll
  for (int i=0;i<2;i++)
#pragma unroll
    for (int j=0;j<4;j++) wmma::fill_fragment(fc[i][j], 0.0f);

  loadTile(0, 0); cp_commit();
  if (KT > 1) loadTile(1, 1);
  cp_commit();

  for (int kt = 0; kt < KT; kt++){
    cp_wait<1>();
    __syncthreads();
    if (kt + 2 < KT) loadTile(kt+2, (kt+2)%3);
    cp_commit();                       // unconditional: keeps wait<1> semantics exact
    const __half* as = As + (kt%3)*STAGE_H;
    const __half* bs = Bs + (kt%3)*STAGE_H;
#pragma unroll
    for (int kk=0; kk<32; kk+=16){
      wmma::fragment<wmma::matrix_a,16,16,16,__half,wmma::row_major> fa[2];
#pragma unroll
      for (int i=0;i<2;i++)
        wmma::load_matrix_sync(fa[i], &as[(wm*32 + i*16)*40 + kk], 40);
      if constexpr (!BT){
#pragma unroll
        for (int j=0;j<4;j++){
          wmma::fragment<wmma::matrix_b,16,16,16,__half,wmma::row_major> fb;
          wmma::load_matrix_sync(fb, &bs[kk*136 + wn*64 + j*16], 136);
#pragma unroll
          for (int i=0;i<2;i++) wmma::mma_sync(fc[i][j], fa[i], fb, fc[i][j]);
        }
      } else {
#pragma unroll
        for (int j=0;j<4;j++){
          wmma::fragment<wmma::matrix_b,16,16,16,__half,wmma::col_major> fb;
          wmma::load_matrix_sync(fb, &bs[(wn*64 + j*16)*40 + kk], 40);
#pragma unroll
          for (int i=0;i<2;i++) wmma::mma_sync(fc[i][j], fa[i], fb, fc[i][j]);
        }
      }
    }
  }

  // ---- epilogue: stage 16x16 tiles through shared, vectorized 16B stores ----
  __syncthreads();                     // done with As/Bs; alias as fp32 staging
  float* Es = reinterpret_cast<float*>(smem);
  float* es = Es + wid*320;            // 16 x 20 floats per warp
  const int r  = lane >> 1;            // 0..15
  const int ch = (lane & 1) * 8;       // 0 or 8
#pragma unroll
  for (int mi=0; mi<2; mi++){
#pragma unroll
    for (int nj=0; nj<4; nj++){
      wmma::store_matrix_sync(es, fc[mi][nj], 20, wmma::mem_row_major);
      __syncwarp();
      float4 v0 = *reinterpret_cast<const float4*>(&es[r*20 + ch]);
      float4 v1 = *reinterpret_cast<const float4*>(&es[r*20 + ch + 4]);
      float vals[8] = {v0.x,v0.y,v0.z,v0.w, v1.x,v1.y,v1.z,v1.w};
      int gr = rm0 + wm*32 + mi*16 + r;
      int gc = cn0 + wn*64 + nj*16 + ch;
      if constexpr (MODE == M_HALF){
        __half h8[8];
#pragma unroll
        for (int e=0;e<8;e++) h8[e] = __float2half(vals[e]);
        *reinterpret_cast<int4*>((__half*)C + (size_t)gr*ldc + gc) = *reinterpret_cast<int4*>(h8);
      } else if constexpr (MODE == M_SCORES){
        __half h8[8];
#pragma unroll
        for (int e=0;e<8;e++){
          float val = vals[e] * 0.17677669529663687f;  // 2/sqrt(128)
          if (gc + e > gr) val = -60000.0f;            // causal mask
          h8[e] = __float2half(val);
        }
        *reinterpret_cast<int4*>((__half*)C + (size_t)z*strC + (size_t)gr*ldc + gc) = *reinterpret_cast<int4*>(h8);
      } else if constexpr (MODE == M_PV){
        int b = z >> 4, h = z & 15;
        __half h8[8];
#pragma unroll
        for (int e=0;e<8;e++) h8[e] = __float2half(vals[e]);
        *reinterpret_cast<int4*>((__half*)C + ((size_t)(b*S_ + gr))*D_ + (size_t)h*DH_ + gc) = *reinterpret_cast<int4*>(h8);
      } else if constexpr (MODE == M_GELU){
        __half h8[8];
#pragma unroll
        for (int e=0;e<8;e++){
          float val = vals[e];
          h8[e] = __float2half(0.5f*val*(1.0f + erff(val*0.70710678118654752f)));
        }
        *reinterpret_cast<int4*>((__half*)C + (size_t)gr*ldc + gc) = *reinterpret_cast<int4*>(h8);
      } else {  // M_WO / M_W2: fp32 out = val + aux
        size_t i2 = (size_t)gr*ldc + gc;
        float4 a0 = *reinterpret_cast<const float4*>(aux + i2);
        float4 a1 = *reinterpret_cast<const float4*>(aux + i2 + 4);
        float4 o0 = make_float4(vals[0]+a0.x, vals[1]+a0.y, vals[2]+a0.z, vals[3]+a0.w);
        float4 o1 = make_float4(vals[4]+a1.x, vals[5]+a1.y, vals[6]+a1.z, vals[7]+a1.w);
        *reinterpret_cast<float4*>((float*)C + i2)     = o0;
        *reinterpret_cast<float4*>((float*)C + i2 + 4) = o1;
      }
      __syncwarp();
    }
  }
}

// ---------------- host ----------------
static void* symaddr(const void* s){
  void* p = nullptr;
  cudaGetSymbolAddress(&p, s);
  return p;
}

extern "C" void kernel_launch(void* const* d_in, const int* in_sizes, int n_in,
                              void* d_out, int out_size) {
  const float* x      = (const float*)d_in[0];
  // d_in[1] = mask (causal tril; handled analytically)
  const float* scale1 = (const float*)d_in[2];
  const float* scale2 = (const float*)d_in[3];
  const float* Wq     = (const float*)d_in[4];
  const float* Wk     = (const float*)d_in[5];
  const float* Wv     = (const float*)d_in[6];
  const float* Wo     = (const float*)d_in[7];
  const float* headK  = (const float*)d_in[8];
  const float* W1     = (const float*)d_in[9];
  const float* W2     = (const float*)d_in[10];

  __half* wq = (__half*)symaddr(g_wq);
  __half* wk = (__half*)symaddr(g_wk);
  __half* wv = (__half*)symaddr(g_wv);
  __half* wo = (__half*)symaddr(g_wo);
  __half* w1 = (__half*)symaddr(g_w1);
  __half* w2 = (__half*)symaddr(g_w2);
  __half* u1 = (__half*)symaddr(g_u1);
  __half* qh = (__half*)symaddr(g_qh);
  __half* kh = (__half*)symaddr(g_kh);
  __half* vh = (__half*)symaddr(g_vh);
  __half* pm = (__half*)symaddr(g_pm);
  __half* ao = (__half*)symaddr(g_ao);
  __half* hid= (__half*)symaddr(g_hid);
  void*   qq = symaddr(g_q);
  void*   kkp= symaddr(g_kk);
  void*   vr = symaddr(g_vr);
  void*   sc = symaddr(g_sc);
  void*   u2 = symaddr(g_u2);
  void*   uf = symaddr(g_uf);
  const float* vlog = (const float*)symaddr(g_v);

  // raise dynamic smem limit for all gemm instantiations (attr set, not an alloc)
  cudaFuncSetAttribute(gemm_k<M_HALF>,   cudaFuncAttributeMaxDynamicSharedMemorySize, SMEM_BYTES);
  cudaFuncSetAttribute(gemm_k<M_SCORES>, cudaFuncAttributeMaxDynamicSharedMemorySize, SMEM_BYTES);
  cudaFuncSetAttribute(gemm_k<M_PV>,     cudaFuncAttributeMaxDynamicSharedMemorySize, SMEM_BYTES);
  cudaFuncSetAttribute(gemm_k<M_WO>,     cudaFuncAttributeMaxDynamicSharedMemorySize, SMEM_BYTES);
  cudaFuncSetAttribute(gemm_k<M_GELU>,   cudaFuncAttributeMaxDynamicSharedMemorySize, SMEM_BYTES);
  cudaFuncSetAttribute(gemm_k<M_W2>,     cudaFuncAttributeMaxDynamicSharedMemorySize, SMEM_BYTES);

  // 1) weights fp32 -> fp16 (vectorized, 8/thread)
  f2h<<<(D_*D_/8  +255)/256,256>>>(Wq, wq, D_*D_);
  f2h<<<(D_*D_/8  +255)/256,256>>>(Wk, wk, D_*D_);
  f2h<<<(D_*D_/8  +255)/256,256>>>(Wv, wv, D_*D_);
  f2h<<<(D_*D_/8  +255)/256,256>>>(Wo, wo, D_*D_);
  f2h<<<(D_*DFF_/8+255)/256,256>>>(W1, w1, D_*DFF_);
  f2h<<<(D_*DFF_/8+255)/256,256>>>(W2, w2, DFF_*D_);

  // 2) log map + rmsnorm-in-log-space
  prep1<<<NROWS,256>>>(x, scale1);

  // 3) QKV projections
  gemm_k<M_HALF><<<dim3(16,32,1),256,SMEM_BYTES>>>(u1, wq, qq,  nullptr, NROWS, D_, D_, D_, D_, D_, 0,0,0);
  gemm_k<M_HALF><<<dim3(16,32,1),256,SMEM_BYTES>>>(u1, wk, kkp, nullptr, NROWS, D_, D_, D_, D_, D_, 0,0,0);
  gemm_k<M_HALF><<<dim3(16,32,1),256,SMEM_BYTES>>>(u1, wv, vr,  nullptr, NROWS, D_, D_, D_, D_, D_, 0,0,0);

  // 4) lift q,k to lorentz 129-dim, v -> head-major
  headprep<<<NROWS,256>>>(headK);

  // 5) scores = (2/sqrt(128)) * q~ . k~, causal mask (masked tiles skipped)
  gemm_k<M_SCORES><<<dim3(16,16,BH_),256,SMEM_BYTES>>>(qh, kh, sc, nullptr,
      S_, S_, DHP_, DHP_, DHP_, S_,
      (long long)S_*DHP_, (long long)S_*DHP_, (long long)S_*S_);

  // 6) softmax per row (causal-bounded)
  softmaxk<<<dim3(S_,BH_),256>>>();

  // 7) P @ V with causal K cap (epilogue writes directly into [b,s,h*dh])
  gemm_k<M_PV><<<dim3(1,16,BH_),256,SMEM_BYTES>>>(pm, vh, ao, nullptr,
      S_, DH_, S_, S_, DH_, DH_,
      (long long)S_*S_, (long long)S_*DH_, 0);

  // 8) attn @ Wo + residual(v) -> u2
  gemm_k<M_WO><<<dim3(16,32,1),256,SMEM_BYTES>>>(ao, wo, u2, vlog,
      NROWS, D_, D_, D_, D_, D_, 0,0,0);

  // 9) rmsnorm in log space (u2)
  prep2<<<NROWS,256>>>(scale2);

  // 10) FFN: gelu(u1 @ W1)
  gemm_k<M_GELU><<<dim3(64,32,1),256,SMEM_BYTES>>>(u1, w1, hid, nullptr,
      NROWS, DFF_, D_, D_, DFF_, DFF_, 0,0,0);

  // 11) hid @ W2 + residual(u2) -> uf
  gemm_k<M_W2><<<dim3(16,32,1),256,SMEM_BYTES>>>(hid, w2, uf, (const float*)u2,
      NROWS, D_, DFF_, DFF_, D_, D_, 0,0,0);

  // 12) final exp map -> output (B,S,2049)
  finalk<<<NROWS,256>>>((float*)d_out);
}